// round 2
// baseline (speedup 1.0000x reference)
#include <cuda_runtime.h>
#include <math.h>

#define N_NODES 100000
#define N_EDGES 320000
#define N_GRAPHS 200
#define EMB 128
#define DD 256
#define STEPS 6
#define HID 128

// ---------------- scratch (device globals; no allocations allowed) ----------
__device__ __align__(16) float g_h  [N_NODES * DD];
__device__ __align__(16) float g_m  [N_NODES * DD];
__device__ __align__(16) float g_agg[N_NODES * DD];
__device__ __align__(16) float g_gi [N_NODES * 3 * DD];
__device__ __align__(16) float g_gh [N_NODES * 3 * DD];
__device__ __align__(16) float g_wT [DD * DD];
__device__ __align__(16) float g_gsum[N_GRAPHS * DD];
__device__ __align__(16) float g_gcnt[N_GRAPHS];

// ---------------- generic C = A @ B^T (+bias), fp32 tiled -------------------
// A: [M,K] row-major, B: [N,K] row-major, C: [M,N]. K % 16 == 0, N % 64 == 0.
__global__ void gemm_abt(const float* __restrict__ A, const float* __restrict__ B,
                         const float* __restrict__ bias, float* __restrict__ C,
                         int M, int N, int K) {
    __shared__ __align__(16) float As[16][64];
    __shared__ __align__(16) float Bs[16][64];
    const int tid = threadIdx.x;
    const int tx  = tid & 15;
    const int ty  = tid >> 4;
    const int bm  = blockIdx.x * 64;
    const int bn  = blockIdx.y * 64;
    const int lrow = tid >> 2;          // 0..63
    const int lcol = (tid & 3) << 2;    // 0,4,8,12

    float acc[4][4];
#pragma unroll
    for (int i = 0; i < 4; i++)
#pragma unroll
        for (int j = 0; j < 4; j++) acc[i][j] = 0.f;

    const bool aval = (bm + lrow) < M;
    const float* Ap = A + (long long)(bm + lrow) * K + lcol;
    const float* Bp = B + (long long)(bn + lrow) * K + lcol;

    for (int k0 = 0; k0 < K; k0 += 16) {
        float4 av = aval ? *(const float4*)(Ap + k0) : make_float4(0.f, 0.f, 0.f, 0.f);
        float4 bv = *(const float4*)(Bp + k0);
        As[lcol + 0][lrow] = av.x; As[lcol + 1][lrow] = av.y;
        As[lcol + 2][lrow] = av.z; As[lcol + 3][lrow] = av.w;
        Bs[lcol + 0][lrow] = bv.x; Bs[lcol + 1][lrow] = bv.y;
        Bs[lcol + 2][lrow] = bv.z; Bs[lcol + 3][lrow] = bv.w;
        __syncthreads();
#pragma unroll
        for (int kk = 0; kk < 16; kk++) {
            float a[4], b[4];
            *(float4*)a = *(const float4*)&As[kk][ty << 2];
            *(float4*)b = *(const float4*)&Bs[kk][tx << 2];
#pragma unroll
            for (int i = 0; i < 4; i++)
#pragma unroll
                for (int j = 0; j < 4; j++) acc[i][j] += a[i] * b[j];
        }
        __syncthreads();
    }

    float4 bb = make_float4(0.f, 0.f, 0.f, 0.f);
    if (bias) bb = *(const float4*)&bias[bn + (tx << 2)];
#pragma unroll
    for (int i = 0; i < 4; i++) {
        int row = bm + (ty << 2) + i;
        if (row < M) {
            float4 v;
            v.x = acc[i][0] + bb.x; v.y = acc[i][1] + bb.y;
            v.z = acc[i][2] + bb.z; v.w = acc[i][3] + bb.w;
            *(float4*)&C[(long long)row * N + bn + (tx << 2)] = v;
        }
    }
}

// ---------------- small helpers ---------------------------------------------
__global__ void transpose256(const float* __restrict__ W, float* __restrict__ WT) {
    int idx = blockIdx.x * 256 + threadIdx.x;   // 65536 threads
    int j = idx >> 8, k = idx & 255;
    WT[idx] = W[k * 256 + j];                   // WT[j][k] = W[k][j]
}

__global__ void zero_kernel(float4* __restrict__ p, int n4) {
    int tid = blockIdx.x * blockDim.x + threadIdx.x;
    if (tid < n4) p[tid] = make_float4(0.f, 0.f, 0.f, 0.f);
}

// agg[dst] += m[src] ; one thread per (edge, 4 columns)
__global__ void scatter_add(const float* __restrict__ m, const int* __restrict__ ei,
                            float* __restrict__ agg) {
    long long tid = (long long)blockIdx.x * blockDim.x + threadIdx.x;
    if (tid >= (long long)N_EDGES * 64) return;
    int e  = (int)(tid >> 6);
    int c4 = (int)(tid & 63) << 2;
    int s  = ei[e];
    int d  = ei[N_EDGES + e];
    float4 v = *(const float4*)&m[(long long)s * DD + c4];
    float* dst = &agg[(long long)d * DD + c4];
    atomicAdd(dst + 0, v.x);
    atomicAdd(dst + 1, v.y);
    atomicAdd(dst + 2, v.z);
    atomicAdd(dst + 3, v.w);
}

__device__ __forceinline__ float sigmoidf(float x) { return 1.f / (1.f + expf(-x)); }

// GRUCell combine: gi/gh buffers already hold agg@Wih^T+bih and h@Whh^T+bhh
__global__ void gru_update(const float* __restrict__ gi, const float* __restrict__ gh,
                           float* __restrict__ h) {
    long long tid = (long long)blockIdx.x * blockDim.x + threadIdx.x;
    if (tid >= (long long)N_NODES * DD) return;
    int n = (int)(tid >> 8);
    int d = (int)(tid & 255);
    const float* gin = gi + (long long)n * 3 * DD;
    const float* ghn = gh + (long long)n * 3 * DD;
    float r  = sigmoidf(gin[d]          + ghn[d]);
    float z  = sigmoidf(gin[DD + d]     + ghn[DD + d]);
    float nn = tanhf   (gin[2 * DD + d] + r * ghn[2 * DD + d]);
    long long hi = (long long)n * DD + d;
    h[hi] = (1.f - z) * nn + z * h[hi];
}

__global__ void pool_sum(const float* __restrict__ h, const int* __restrict__ batch,
                         float* __restrict__ gsum) {
    long long tid = (long long)blockIdx.x * blockDim.x + threadIdx.x;
    if (tid >= (long long)N_NODES * 64) return;
    int n  = (int)(tid >> 6);
    int c4 = (int)(tid & 63) << 2;
    int g  = batch[n];
    float4 v = *(const float4*)&h[(long long)n * DD + c4];
    float* dst = &gsum[g * DD + c4];
    atomicAdd(dst + 0, v.x);
    atomicAdd(dst + 1, v.y);
    atomicAdd(dst + 2, v.z);
    atomicAdd(dst + 3, v.w);
}

__global__ void pool_cnt(const int* __restrict__ batch, float* __restrict__ gcnt) {
    int n = blockIdx.x * blockDim.x + threadIdx.x;
    if (n < N_NODES) atomicAdd(&gcnt[batch[n]], 1.f);
}

// One block per graph: mean -> relu(W1 x + b1) -> W2 h + b2 -> sigmoid
__global__ void classifier(const float* __restrict__ gsum, const float* __restrict__ gcnt,
                           const float* __restrict__ w1, const float* __restrict__ b1,
                           const float* __restrict__ w2, const float* __restrict__ b2,
                           float* __restrict__ out) {
    int g = blockIdx.x, t = threadIdx.x;   // 128 threads
    __shared__ float repr[DD];
    __shared__ float red[HID];
    float inv = 1.f / fmaxf(gcnt[g], 1.f);
    repr[t]        = gsum[g * DD + t] * inv;
    repr[t + HID]  = gsum[g * DD + t + HID] * inv;
    __syncthreads();
    float acc = b1[t];
    const float* w = w1 + t * DD;
#pragma unroll 8
    for (int k = 0; k < DD; k++) acc += repr[k] * w[k];
    red[t] = fmaxf(acc, 0.f) * w2[t];
    __syncthreads();
    for (int s = 64; s > 0; s >>= 1) {
        if (t < s) red[t] += red[t + s];
        __syncthreads();
    }
    if (t == 0) out[g] = 1.f / (1.f + expf(-(red[0] + b2[0])));
}

// ---------------- launch -----------------------------------------------------
static void run_gemm(const float* A, const float* B, const float* bias, float* C,
                     int M, int N, int K) {
    dim3 grid((M + 63) / 64, N / 64);
    gemm_abt<<<grid, 256>>>(A, B, bias, C, M, N, K);
}

extern "C" void kernel_launch(void* const* d_in, const int* in_sizes, int n_in,
                              void* d_out, int out_size) {
    const float* x      = (const float*)d_in[0];
    const float* lin_w  = (const float*)d_in[1];
    const float* lin_b  = (const float*)d_in[2];
    const float* ggnn_w = (const float*)d_in[3];
    const float* w_ih   = (const float*)d_in[4];
    const float* w_hh   = (const float*)d_in[5];
    const float* b_ih   = (const float*)d_in[6];
    const float* b_hh   = (const float*)d_in[7];
    const float* cls_w1 = (const float*)d_in[8];
    const float* cls_b1 = (const float*)d_in[9];
    const float* cls_w2 = (const float*)d_in[10];
    const float* cls_b2 = (const float*)d_in[11];
    const int* edge_index = (const int*)d_in[12];   // int32 (JAX x64 disabled)
    const int* batch      = (const int*)d_in[13];   // int32
    float* out = (float*)d_out;

    float *h, *m, *agg, *gi, *gh, *wT, *gsum, *gcnt;
    cudaGetSymbolAddress((void**)&h,    g_h);
    cudaGetSymbolAddress((void**)&m,    g_m);
    cudaGetSymbolAddress((void**)&agg,  g_agg);
    cudaGetSymbolAddress((void**)&gi,   g_gi);
    cudaGetSymbolAddress((void**)&gh,   g_gh);
    cudaGetSymbolAddress((void**)&wT,   g_wT);
    cudaGetSymbolAddress((void**)&gsum, g_gsum);
    cudaGetSymbolAddress((void**)&gcnt, g_gcnt);

    // h = x @ lin_w^T + lin_b
    run_gemm(x, lin_w, lin_b, h, N_NODES, DD, EMB);

    const int ND4 = N_NODES * DD / 4;
    for (int s = 0; s < STEPS; s++) {
        transpose256<<<256, 256>>>(ggnn_w + (long long)s * DD * DD, wT);
        // m = h @ W[s]  ==  h @ wT^T
        run_gemm(h, wT, nullptr, m, N_NODES, DD, DD);
        zero_kernel<<<(ND4 + 255) / 256, 256>>>((float4*)agg, ND4);
        scatter_add<<<(int)(((long long)N_EDGES * 64 + 255) / 256), 256>>>(m, edge_index, agg);
        // gi = agg @ w_ih^T + b_ih ; gh = h @ w_hh^T + b_hh
        run_gemm(agg, w_ih, b_ih, gi, N_NODES, 3 * DD, DD);
        run_gemm(h,   w_hh, b_hh, gh, N_NODES, 3 * DD, DD);
        gru_update<<<(int)(((long long)N_NODES * DD + 255) / 256), 256>>>(gi, gh, h);
    }

    zero_kernel<<<(N_GRAPHS * DD / 4 + 255) / 256, 256>>>((float4*)gsum, N_GRAPHS * DD / 4);
    zero_kernel<<<1, 64>>>((float4*)gcnt, N_GRAPHS / 4);
    pool_sum<<<(int)(((long long)N_NODES * 64 + 255) / 256), 256>>>(h, batch, gsum);
    pool_cnt<<<(N_NODES + 255) / 256, 256>>>(batch, gcnt);
    classifier<<<N_GRAPHS, HID>>>(gsum, gcnt, cls_w1, cls_b1, cls_w2, cls_b2, out);
}

// round 4
// speedup vs baseline: 2.9434x; 2.9434x over previous
#include <cuda_runtime.h>
#include <math.h>
#include <stdint.h>

#define N_NODES 100000
#define N_EDGES 320000
#define N_GRAPHS 200
#define EMB 128
#define DD 256
#define STEPS 6
#define HID 128

// ---------------- scratch (device globals; no allocations allowed) ----------
__device__ __align__(16) float g_h  [N_NODES * DD];
__device__ __align__(16) float g_m  [N_NODES * DD];
__device__ __align__(16) float g_agg[N_NODES * DD];
__device__ __align__(16) float g_gi [N_NODES * 3 * DD];
__device__ __align__(16) float g_gh [N_NODES * 3 * DD];
__device__ __align__(16) float g_wT [DD * DD];
__device__ __align__(16) float g_gsum[N_GRAPHS * DD];
__device__ __align__(16) float g_gcnt[N_GRAPHS];

// =============== tf32 mma.sync GEMM:  C = A @ B^T (+bias) ===================
// A: [M,K] row-major fp32, B: [N,K] row-major fp32, C: [M,N].
// K % 32 == 0, N % 128 == 0. Tile 128x128, 8 warps (4m x 2n), warp 32x64.
#define BM 128
#define BN 128
#define BK 32
#define PAD 36                       // floats per smem row: bank = (4r+c)%32 -> conflict-free
#define GT  256
#define TBUF (BM * PAD)              // floats per stage buffer
#define GEMM_SMEM (4 * TBUF * 4)     // A[2] + B[2] buffers = 73728 bytes

__device__ __forceinline__ uint32_t smem_u32(const void* p) {
    uint32_t a;
    asm("{ .reg .u64 t; cvta.to.shared.u64 t, %1; cvt.u32.u64 %0, t; }" : "=r"(a) : "l"(p));
    return a;
}

__device__ __forceinline__ uint32_t f2tf32(float f) {
    uint32_t u;
    asm("cvt.rna.tf32.f32 %0, %1;" : "=r"(u) : "f"(f));
    return u;
}

__device__ __forceinline__ void cp16(uint32_t dst, const float* src) {
    asm volatile("cp.async.cg.shared.global [%0], [%1], 16;" :: "r"(dst), "l"(src));
}
__device__ __forceinline__ void cp16z(uint32_t dst, const float* src, int pred) {
    // pred==0 -> zero-fill 16 bytes (src not accessed)
    asm volatile("cp.async.cg.shared.global [%0], [%1], 16, %2;"
                 :: "r"(dst), "l"(src), "r"(pred ? 16 : 0));
}

__global__ __launch_bounds__(GT, 2)
void gemm_mma(const float* __restrict__ A, const float* __restrict__ B,
              const float* __restrict__ bias, float* __restrict__ C,
              int M, int N, int K) {
    extern __shared__ __align__(16) float sm[];
    float* Asm = sm;              // [2][TBUF]
    float* Bsm = sm + 2 * TBUF;   // [2][TBUF]
    const uint32_t as0 = smem_u32(Asm);
    const uint32_t bs0 = smem_u32(Bsm);

    const int tid  = threadIdx.x;
    const int wid  = tid >> 5;
    const int lane = tid & 31;
    const int g    = lane >> 2;     // 0..7
    const int t4   = lane & 3;      // 0..3
    const int wm   = (wid >> 1) * 32;
    const int wn   = (wid & 1) * 64;
    const int bm   = blockIdx.x * BM;
    const int bn   = blockIdx.y * BN;
    const int KC   = K / BK;

    float acc[2][8][4];
#pragma unroll
    for (int i = 0; i < 2; i++)
#pragma unroll
        for (int j = 0; j < 8; j++)
#pragma unroll
            for (int q = 0; q < 4; q++) acc[i][j][q] = 0.f;

    auto load_chunk = [&](int c, int buf) {
        const float* Ag = A + (size_t)bm * K + c * BK;
        const float* Bg = B + (size_t)bn * K + c * BK;
        const uint32_t abase = as0 + buf * (TBUF * 4);
        const uint32_t bbase = bs0 + buf * (TBUF * 4);
#pragma unroll
        for (int i = 0; i < 4; i++) {
            int idx = tid + i * GT;          // 0..1023
            int row = idx >> 3, f4 = idx & 7;
            cp16z(abase + (row * PAD + f4 * 4) * 4,
                  Ag + (size_t)row * K + f4 * 4, (bm + row) < M);
        }
#pragma unroll
        for (int i = 0; i < 4; i++) {
            int idx = tid + i * GT;
            int row = idx >> 3, f4 = idx & 7;
            cp16(bbase + (row * PAD + f4 * 4) * 4,
                 Bg + (size_t)row * K + f4 * 4);
        }
        asm volatile("cp.async.commit_group;" ::: "memory");
    };

    load_chunk(0, 0);
    for (int c = 0; c < KC; c++) {
        const int buf = c & 1;
        if (c + 1 < KC) {
            load_chunk(c + 1, buf ^ 1);
            asm volatile("cp.async.wait_group 1;" ::: "memory");
        } else {
            asm volatile("cp.async.wait_group 0;" ::: "memory");
        }
        __syncthreads();

        const float* Ab = Asm + buf * TBUF;
        const float* Bb = Bsm + buf * TBUF;
#pragma unroll
        for (int ks = 0; ks < 4; ks++) {
            const int k0 = ks * 8;
            uint32_t a[2][4], b[8][2];
#pragma unroll
            for (int i = 0; i < 2; i++) {
                int r = wm + 16 * i + g;
                a[i][0] = f2tf32(Ab[r * PAD + k0 + t4]);
                a[i][1] = f2tf32(Ab[(r + 8) * PAD + k0 + t4]);
                a[i][2] = f2tf32(Ab[r * PAD + k0 + 4 + t4]);
                a[i][3] = f2tf32(Ab[(r + 8) * PAD + k0 + 4 + t4]);
            }
#pragma unroll
            for (int j = 0; j < 8; j++) {
                int n = wn + 8 * j + g;
                b[j][0] = f2tf32(Bb[n * PAD + k0 + t4]);
                b[j][1] = f2tf32(Bb[n * PAD + k0 + 4 + t4]);
            }
#pragma unroll
            for (int i = 0; i < 2; i++)
#pragma unroll
                for (int j = 0; j < 8; j++) {
                    asm volatile(
                        "mma.sync.aligned.m16n8k8.row.col.f32.tf32.tf32.f32 "
                        "{%0,%1,%2,%3}, {%4,%5,%6,%7}, {%8,%9}, {%0,%1,%2,%3};"
                        : "+f"(acc[i][j][0]), "+f"(acc[i][j][1]),
                          "+f"(acc[i][j][2]), "+f"(acc[i][j][3])
                        : "r"(a[i][0]), "r"(a[i][1]), "r"(a[i][2]), "r"(a[i][3]),
                          "r"(b[j][0]), "r"(b[j][1]));
                }
        }
        __syncthreads();
    }

    // epilogue
#pragma unroll
    for (int i = 0; i < 2; i++) {
        int r0 = bm + wm + 16 * i + g;
#pragma unroll
        for (int j = 0; j < 8; j++) {
            int col = bn + wn + 8 * j + t4 * 2;
            float2 bb = make_float2(0.f, 0.f);
            if (bias) bb = *(const float2*)(bias + col);
            if (r0 < M) {
                float2 v = make_float2(acc[i][j][0] + bb.x, acc[i][j][1] + bb.y);
                *(float2*)&C[(size_t)r0 * N + col] = v;
            }
            if (r0 + 8 < M) {
                float2 v = make_float2(acc[i][j][2] + bb.x, acc[i][j][3] + bb.y);
                *(float2*)&C[(size_t)(r0 + 8) * N + col] = v;
            }
        }
    }
}

// ---------------- small helpers ---------------------------------------------
__global__ void transpose256(const float* __restrict__ W, float* __restrict__ WT) {
    int idx = blockIdx.x * 256 + threadIdx.x;
    int j = idx >> 8, k = idx & 255;
    WT[idx] = W[k * 256 + j];
}

__global__ void zero_kernel(float4* __restrict__ p, int n4) {
    int tid = blockIdx.x * blockDim.x + threadIdx.x;
    if (tid < n4) p[tid] = make_float4(0.f, 0.f, 0.f, 0.f);
}

__global__ void scatter_add(const float* __restrict__ m, const int* __restrict__ ei,
                            float* __restrict__ agg) {
    long long tid = (long long)blockIdx.x * blockDim.x + threadIdx.x;
    if (tid >= (long long)N_EDGES * 64) return;
    int e  = (int)(tid >> 6);
    int c4 = (int)(tid & 63) << 2;
    int s  = ei[e];
    int d  = ei[N_EDGES + e];
    float4 v = *(const float4*)&m[(long long)s * DD + c4];
    float* dst = &agg[(long long)d * DD + c4];
    atomicAdd(dst + 0, v.x);
    atomicAdd(dst + 1, v.y);
    atomicAdd(dst + 2, v.z);
    atomicAdd(dst + 3, v.w);
}

__device__ __forceinline__ float sigmoidf(float x) { return 1.f / (1.f + expf(-x)); }

__global__ void gru_update(const float4* __restrict__ gi, const float4* __restrict__ gh,
                           float4* __restrict__ h) {
    int tid = blockIdx.x * blockDim.x + threadIdx.x;
    if (tid >= N_NODES * 64) return;
    int n = tid >> 6, d4 = tid & 63;
    const float4* gin = gi + (size_t)n * 192;
    const float4* ghn = gh + (size_t)n * 192;
    float4 ir = gin[d4], iz = gin[64 + d4], in_ = gin[128 + d4];
    float4 hr = ghn[d4], hz = ghn[64 + d4], hn = ghn[128 + d4];
    float4 hv = h[(size_t)n * 64 + d4];
    float4 o;
    {
        float r = sigmoidf(ir.x + hr.x), z = sigmoidf(iz.x + hz.x);
        float nn = tanhf(in_.x + r * hn.x);
        o.x = (1.f - z) * nn + z * hv.x;
    }
    {
        float r = sigmoidf(ir.y + hr.y), z = sigmoidf(iz.y + hz.y);
        float nn = tanhf(in_.y + r * hn.y);
        o.y = (1.f - z) * nn + z * hv.y;
    }
    {
        float r = sigmoidf(ir.z + hr.z), z = sigmoidf(iz.z + hz.z);
        float nn = tanhf(in_.z + r * hn.z);
        o.z = (1.f - z) * nn + z * hv.z;
    }
    {
        float r = sigmoidf(ir.w + hr.w), z = sigmoidf(iz.w + hz.w);
        float nn = tanhf(in_.w + r * hn.w);
        o.w = (1.f - z) * nn + z * hv.w;
    }
    h[(size_t)n * 64 + d4] = o;
}

__global__ void pool_sum(const float* __restrict__ h, const int* __restrict__ batch,
                         float* __restrict__ gsum) {
    long long tid = (long long)blockIdx.x * blockDim.x + threadIdx.x;
    if (tid >= (long long)N_NODES * 64) return;
    int n  = (int)(tid >> 6);
    int c4 = (int)(tid & 63) << 2;
    int g  = batch[n];
    float4 v = *(const float4*)&h[(long long)n * DD + c4];
    float* dst = &gsum[g * DD + c4];
    atomicAdd(dst + 0, v.x);
    atomicAdd(dst + 1, v.y);
    atomicAdd(dst + 2, v.z);
    atomicAdd(dst + 3, v.w);
}

__global__ void pool_cnt(const int* __restrict__ batch, float* __restrict__ gcnt) {
    int n = blockIdx.x * blockDim.x + threadIdx.x;
    if (n < N_NODES) atomicAdd(&gcnt[batch[n]], 1.f);
}

__global__ void classifier(const float* __restrict__ gsum, const float* __restrict__ gcnt,
                           const float* __restrict__ w1, const float* __restrict__ b1,
                           const float* __restrict__ w2, const float* __restrict__ b2,
                           float* __restrict__ out) {
    int g = blockIdx.x, t = threadIdx.x;   // 128 threads
    __shared__ float repr[DD];
    __shared__ float red[HID];
    float inv = 1.f / fmaxf(gcnt[g], 1.f);
    repr[t]       = gsum[g * DD + t] * inv;
    repr[t + HID] = gsum[g * DD + t + HID] * inv;
    __syncthreads();
    float acc = b1[t];
    const float* w = w1 + t * DD;
#pragma unroll 8
    for (int k = 0; k < DD; k++) acc += repr[k] * w[k];
    red[t] = fmaxf(acc, 0.f) * w2[t];
    __syncthreads();
    for (int s = 64; s > 0; s >>= 1) {
        if (t < s) red[t] += red[t + s];
        __syncthreads();
    }
    if (t == 0) out[g] = 1.f / (1.f + expf(-(red[0] + b2[0])));
}

// ---------------- launch -----------------------------------------------------
static void run_gemm(const float* A, const float* B, const float* bias, float* C,
                     int M, int N, int K) {
    dim3 grid((M + BM - 1) / BM, N / BN);
    gemm_mma<<<grid, GT, GEMM_SMEM>>>(A, B, bias, C, M, N, K);
}

extern "C" void kernel_launch(void* const* d_in, const int* in_sizes, int n_in,
                              void* d_out, int out_size) {
    const float* x      = (const float*)d_in[0];
    const float* lin_w  = (const float*)d_in[1];
    const float* lin_b  = (const float*)d_in[2];
    const float* ggnn_w = (const float*)d_in[3];
    const float* w_ih   = (const float*)d_in[4];
    const float* w_hh   = (const float*)d_in[5];
    const float* b_ih   = (const float*)d_in[6];
    const float* b_hh   = (const float*)d_in[7];
    const float* cls_w1 = (const float*)d_in[8];
    const float* cls_b1 = (const float*)d_in[9];
    const float* cls_w2 = (const float*)d_in[10];
    const float* cls_b2 = (const float*)d_in[11];
    const int* edge_index = (const int*)d_in[12];
    const int* batch      = (const int*)d_in[13];
    float* out = (float*)d_out;

    float *h, *m, *agg, *gi, *gh, *wT, *gsum, *gcnt;
    cudaGetSymbolAddress((void**)&h,    g_h);
    cudaGetSymbolAddress((void**)&m,    g_m);
    cudaGetSymbolAddress((void**)&agg,  g_agg);
    cudaGetSymbolAddress((void**)&gi,   g_gi);
    cudaGetSymbolAddress((void**)&gh,   g_gh);
    cudaGetSymbolAddress((void**)&wT,   g_wT);
    cudaGetSymbolAddress((void**)&gsum, g_gsum);
    cudaGetSymbolAddress((void**)&gcnt, g_gcnt);

    cudaFuncSetAttribute(gemm_mma, cudaFuncAttributeMaxDynamicSharedMemorySize, GEMM_SMEM);

    // h = x @ lin_w^T + lin_b
    run_gemm(x, lin_w, lin_b, h, N_NODES, DD, EMB);

    const int ND4 = N_NODES * DD / 4;
    for (int s = 0; s < STEPS; s++) {
        transpose256<<<256, 256>>>(ggnn_w + (long long)s * DD * DD, wT);
        run_gemm(h, wT, nullptr, m, N_NODES, DD, DD);          // m = h @ W[s]
        zero_kernel<<<(ND4 + 255) / 256, 256>>>((float4*)agg, ND4);
        scatter_add<<<(int)(((long long)N_EDGES * 64 + 255) / 256), 256>>>(m, edge_index, agg);
        run_gemm(agg, w_ih, b_ih, gi, N_NODES, 3 * DD, DD);    // gi
        run_gemm(h,   w_hh, b_hh, gh, N_NODES, 3 * DD, DD);    // gh
        gru_update<<<(N_NODES * 64 + 255) / 256, 256>>>((const float4*)gi, (const float4*)gh,
                                                        (float4*)h);
    }

    zero_kernel<<<(N_GRAPHS * DD / 4 + 255) / 256, 256>>>((float4*)gsum, N_GRAPHS * DD / 4);
    zero_kernel<<<1, 64>>>((float4*)gcnt, N_GRAPHS / 4);
    pool_sum<<<(int)(((long long)N_NODES * 64 + 255) / 256), 256>>>(h, batch, gsum);
    pool_cnt<<<(N_NODES + 255) / 256, 256>>>(batch, gcnt);
    classifier<<<N_GRAPHS, HID>>>(gsum, gcnt, cls_w1, cls_b1, cls_w2, cls_b2, out);
}